// round 10
// baseline (speedup 1.0000x reference)
#include <cuda_runtime.h>
#include <cuda_bf16.h>
#include <cstdint>
#include <cstddef>

// Problem constants
#define BQ 256          // batch
#define NN 256          // nodes
#define FF 67           // fp feature stride
#define FEAT 64         // used features
#define HID 400
#define EGO 62          // STATE_DIM + 1
#define BFP (NN * FF)   // 17152 floats per batch in fp
#define CH 128          // nodes per smem chunk in k_attn

// fc1 GEMM tiling
#define TT 80           // t-outputs per block (5 tiles cover 400)
#define KG3 40          // k per k-group (10 groups cover 400)

// ---------------- scratch (device globals; no allocs allowed) ----------------
__device__ float g_wl_u[FEAT], g_wr_u[FEAT], g_wl_d[FEAT], g_wr_d[FEAT];
__device__ float g_c2u[HID], g_c2d[HID];
__device__ float g_fbar_u[BQ * FEAT];
__device__ float g_fbar_d[BQ * FEAT];
__device__ __align__(16) float g_H0[BQ * HID];   // relu(ego@fc0)
__device__ float g_Qs[BQ];                       // fc2 partial sums (atomic)
__device__ unsigned int g_cnt[BQ / 8];           // finalize counters

__device__ __forceinline__ float eluf(float x) {
    return x > 0.f ? x : (expf(x) - 1.f);
}

// ---------------- K0: prep (warp-per-output) + H0 ----------------------------
// blocks [0,133):   1056 warps of dot products + zero block
// blocks [133,165): H0 = relu(ego@fc0+b), 8 batches per block
__global__ void __launch_bounds__(256) k_prep(
        const float* __restrict__ u1W, const float* __restrict__ u1a,
        const float* __restrict__ d1W, const float* __restrict__ d1a,
        const float* __restrict__ u2W, const float* __restrict__ d2W,
        const float* __restrict__ fc3w, float* __restrict__ reg_out,
        const float* __restrict__ x, const float* __restrict__ a,
        const float* __restrict__ fc0w, const float* __restrict__ fc0b) {
    if (blockIdx.x < 133) {
        const int warp = blockIdx.x * 8 + (threadIdx.x >> 5);
        const int lane = threadIdx.x & 31;
        if (warp < 1056) {
            const float* Wrow;
            const float* v;
            float* dst;
            if (warp < 256) {
                int which = warp >> 6, f = warp & 63;
                const float* W  = (which < 2) ? u1W : d1W;
                const float* av = (which < 2) ? u1a : d1a;
                Wrow = W + (size_t)f * HID;
                v    = av + ((which & 1) ? HID : 0);
                dst  = (which == 0) ? g_wl_u + f : (which == 1) ? g_wr_u + f
                     : (which == 2) ? g_wl_d + f : g_wr_d + f;
            } else {
                int k = warp - 256;
                const float* W = (k < HID) ? u2W : d2W;
                int kk = (k < HID) ? k : k - HID;
                Wrow = W + (size_t)kk * HID;
                v    = fc3w;
                dst  = (k < HID) ? g_c2u + kk : g_c2d + kk;
            }
            float s = 0.f;
            #pragma unroll
            for (int i = 0; i < 13; i++) {
                int idx = lane + 32 * i;
                if (idx < HID) s = fmaf(Wrow[idx], v[idx], s);
            }
            #pragma unroll
            for (int o = 16; o > 0; o >>= 1) s += __shfl_down_sync(0xffffffffu, s, o);
            if (lane == 0) *dst = s;
        } else if (warp == 1056) {
            for (int i = lane; i < BQ; i += 32) g_Qs[i] = 0.f;
            g_cnt[lane] = 0u;
            if (lane == 0) reg_out[0] = 0.f;
        }
        return;
    }

    // ---- H0 blocks ----
    const int b0 = (blockIdx.x - 133) * 8;
    const int tid = threadIdx.x;
    __shared__ __align__(16) float egoT[EGO][8];     // [feat][batch]
    for (int i = tid; i < 8 * EGO; i += 256) {
        int b = i / EGO, f = i % EGO;
        egoT[f][b] = (f < 61) ? x[(size_t)(b0 + b) * 61 + f] : a[b0 + b];
    }
    __syncthreads();

    #pragma unroll
    for (int rep = 0; rep < 2; rep++) {
        int t = tid + rep * 256;
        if (t < HID) {
            float bias = fc0b[t];
            float acc[8];
            #pragma unroll
            for (int b = 0; b < 8; b++) acc[b] = bias;
            #pragma unroll
            for (int f = 0; f < EGO; f++) {
                float w = fc0w[f * HID + t];
                const float4* e4 = (const float4*)egoT[f];
                float4 e0 = e4[0], e1 = e4[1];
                acc[0] = fmaf(e0.x, w, acc[0]);
                acc[1] = fmaf(e0.y, w, acc[1]);
                acc[2] = fmaf(e0.z, w, acc[2]);
                acc[3] = fmaf(e0.w, w, acc[3]);
                acc[4] = fmaf(e1.x, w, acc[4]);
                acc[5] = fmaf(e1.y, w, acc[5]);
                acc[6] = fmaf(e1.z, w, acc[6]);
                acc[7] = fmaf(e1.w, w, acc[7]);
            }
            #pragma unroll
            for (int b = 0; b < 8; b++)
                g_H0[(size_t)(b0 + b) * HID + t] = fmaxf(acc[b], 0.f);
        }
    }
}

// ---------------- K1: per-batch star attention -> featbar ---------------------
// single-pass online softmax; fp staged into smem ONCE per block.
__global__ void __launch_bounds__(256) k_attn(const float* __restrict__ fp) {
    const int b = blockIdx.x, t = threadIdx.x;
    const int lane = t & 31, wid = t >> 5;
    const int f = t & 63, g = t >> 6;          // pass-2 role: 4 groups x 64 feats

    __shared__ __align__(16) float buf[CH * FF];     // 34.3KB chunk
    __shared__ float wlu[FEAT], wru[FEAT], wld[FEAT], wrd[FEAT];
    __shared__ float ps_u[CH], ps_d[CH];
    __shared__ float red[NN], red2[NN];
    __shared__ float smxu[4], smxd[4], smsu[4], smsd[4];
    __shared__ float scal[2];

    if (t < FEAT) { wlu[t] = g_wl_u[t]; wru[t] = g_wr_u[t];
                    wld[t] = g_wl_d[t]; wrd[t] = g_wr_d[t]; }

    float M_u = -3.4e38f, M_d = -3.4e38f;
    float S_u = 0.f, S_d = 0.f;
    float fb_u = 0.f, fb_d = 0.f;

    #pragma unroll
    for (int c = 0; c < 2; c++) {
        __syncthreads();   // buf/ps consumers of previous chunk done
        {
            const float4* src = (const float4*)(fp + (size_t)b * BFP + (size_t)c * CH * FF);
            float4* dbuf = (float4*)buf;
            #pragma unroll
            for (int i = 0; i < 9; i++) {
                int idx = t + 256 * i;
                if (idx < CH * FF / 4) dbuf[idx] = src[idx];
            }
        }
        __syncthreads();

        float su = 0.f, sd = 0.f;
        if (t < CH) {
            const float* row = buf + t * FF;
            float lu = 0.f, ld = 0.f;
            #pragma unroll 16
            for (int ff = 0; ff < FEAT; ff++) {
                float v = row[ff];
                su = fmaf(v, wru[ff], su);
                sd = fmaf(v, wrd[ff], sd);
                lu = fmaf(v, wlu[ff], lu);
                ld = fmaf(v, wld[ff], ld);
            }
            if (c == 0 && t == 0) { scal[0] = lu; scal[1] = ld; }
        }
        __syncthreads();   // scal ready

        float eu = 0.f, ed = 0.f;
        if (t < CH) {
            eu = scal[0] + su;  eu = eu > 0.f ? eu : 0.2f * eu;
            ed = scal[1] + sd;  ed = ed > 0.f ? ed : 0.2f * ed;
            if (c == 0 && t == 0) { eu = -1e30f; ed = -1e30f; }
            float mu = eu, md = ed;
            #pragma unroll
            for (int o = 16; o > 0; o >>= 1) {
                mu = fmaxf(mu, __shfl_xor_sync(0xffffffffu, mu, o));
                md = fmaxf(md, __shfl_xor_sync(0xffffffffu, md, o));
            }
            if (lane == 0) { smxu[wid] = mu; smxd[wid] = md; }
        }
        __syncthreads();
        float mcu = fmaxf(fmaxf(smxu[0], smxu[1]), fmaxf(smxu[2], smxu[3]));
        float mcd = fmaxf(fmaxf(smxd[0], smxd[1]), fmaxf(smxd[2], smxd[3]));
        float Mn_u = fmaxf(M_u, mcu), Mn_d = fmaxf(M_d, mcd);

        if (t < CH) {
            float pu = expf(eu - Mn_u), pd = expf(ed - Mn_d);
            ps_u[t] = pu;  ps_d[t] = pd;
            float tu = pu, td = pd;
            #pragma unroll
            for (int o = 16; o > 0; o >>= 1) {
                tu += __shfl_xor_sync(0xffffffffu, tu, o);
                td += __shfl_xor_sync(0xffffffffu, td, o);
            }
            if (lane == 0) { smsu[wid] = tu; smsd[wid] = td; }
        }
        __syncthreads();   // ps + sums ready
        float sumu = smsu[0] + smsu[1] + smsu[2] + smsu[3];
        float sumd = smsd[0] + smsd[1] + smsd[2] + smsd[3];
        float rs_u = expf(M_u - Mn_u);     // 0 on first chunk
        float rs_d = expf(M_d - Mn_d);
        S_u = S_u * rs_u + sumu;   S_d = S_d * rs_d + sumd;
        fb_u *= rs_u;              fb_d *= rs_d;
        M_u = Mn_u;                M_d = Mn_d;

        // featbar partial: group g covers chunk-local nodes [g*32, g*32+32)
        const float* col = buf + (g * 32) * FF + f;
        #pragma unroll 8
        for (int i = 0; i < 32; i++) {
            float v = col[i * FF];
            fb_u = fmaf(ps_u[g * 32 + i], v, fb_u);
            fb_d = fmaf(ps_d[g * 32 + i], v, fb_d);
        }
    }

    red[t] = fb_u; red2[t] = fb_d; __syncthreads();
    if (t < 64) {
        g_fbar_u[b * FEAT + t] =
            (red[t] + red[t + 64] + red[t + 128] + red[t + 192]) / S_u;
        g_fbar_d[b * FEAT + t] =
            (red2[t] + red2[t + 64] + red2[t + 128] + red2[t + 192]) / S_d;
    }
}

// ---------------- K2: GAT layer1 matvecs + collapsed head -> A ----------------
__global__ void __launch_bounds__(512) k_gat2(const float* __restrict__ fp,
                                              const float* __restrict__ u1W,
                                              const float* __restrict__ d1W,
                                              const float* __restrict__ fc3b,
                                              float* __restrict__ A_out) {
    const int b0 = blockIdx.x * 4, t = threadIdx.x;
    __shared__ float x0[4][FEAT], xu[4][FEAT], xd[4][FEAT];
    __shared__ float c2u[HID], c2d[HID];
    __shared__ float sm_part[16][4];

    if (t < 256) {
        int r = t >> 6, f = t & 63;
        x0[r][f] = fp[(size_t)(b0 + r) * BFP + f];
        xu[r][f] = g_fbar_u[(b0 + r) * FEAT + f];
        xd[r][f] = g_fbar_d[(b0 + r) * FEAT + f];
    }
    if (t < HID) { c2u[t] = g_c2u[t]; c2d[t] = g_c2d[t]; }
    __syncthreads();

    float Av[4] = {0.f, 0.f, 0.f, 0.f};
    if (t < HID) {
        float a0[4] = {0.f, 0.f, 0.f, 0.f};
        float a1[4] = {0.f, 0.f, 0.f, 0.f};
        #pragma unroll 8
        for (int f = 0; f < FEAT; f++) {
            float w = u1W[f * HID + t];
            #pragma unroll
            for (int r = 0; r < 4; r++) {
                a0[r] = fmaf(x0[r][f], w, a0[r]);
                a1[r] = fmaf(xu[r][f], w, a1[r]);
            }
        }
        float cu = c2u[t];
        #pragma unroll
        for (int r = 0; r < 4; r++)
            Av[r] = (eluf(a0[r]) + 255.f * eluf(a1[r])) * cu;

        #pragma unroll
        for (int r = 0; r < 4; r++) { a0[r] = 0.f; a1[r] = 0.f; }
        #pragma unroll 8
        for (int f = 0; f < FEAT; f++) {
            float w = d1W[f * HID + t];
            #pragma unroll
            for (int r = 0; r < 4; r++) {
                a0[r] = fmaf(x0[r][f], w, a0[r]);
                a1[r] = fmaf(xd[r][f], w, a1[r]);
            }
        }
        float cd = c2d[t];
        #pragma unroll
        for (int r = 0; r < 4; r++)
            Av[r] += (eluf(a0[r]) + 255.f * eluf(a1[r])) * cd;
    }

    #pragma unroll
    for (int r = 0; r < 4; r++) {
        float s = Av[r];
        #pragma unroll
        for (int o = 16; o > 0; o >>= 1) s += __shfl_down_sync(0xffffffffu, s, o);
        if ((t & 31) == 0) sm_part[t >> 5][r] = s;
    }
    __syncthreads();
    if (t < 4) {
        float s = 0.f;
        #pragma unroll
        for (int wi = 0; wi < 16; wi++) s += sm_part[wi][t];
        A_out[b0 + t] = s + fc3b[0];
    }
}

// ---------------- K3: fc1+relu+fc2 partials + finalize ------------------------
// grid (32 batch-tiles of 8, 5 t-tiles). 800 thr = 80 t-lanes x 10 k-groups of 40.
// 4-k-wide inner step: float4 H0 loads (g*40 is 16B-aligned), fully unrolled.
__global__ void __launch_bounds__(800) k_ego(const float* __restrict__ fc1w,
                                             const float* __restrict__ fc1b,
                                             const float* __restrict__ fc2w,
                                             const float* __restrict__ fc2b,
                                             const float* __restrict__ A_in,
                                             float* __restrict__ Q_out,
                                             float* __restrict__ G_out) {
    const int b0 = blockIdx.x * 8;
    const int t0 = blockIdx.y * TT;
    const int tid = threadIdx.x;

    __shared__ __align__(16) float H0s[8][HID];      // 12.8KB
    __shared__ float part[10][TT][8];                // 25.6KB
    __shared__ int sflag;

    // stage H0 (contiguous 8*400 floats = 800 float4s, exactly 1 per thread)
    {
        const float4* hsrc = (const float4*)(g_H0 + (size_t)b0 * HID);
        ((float4*)&H0s[0][0])[tid] = hsrc[tid];
    }
    __syncthreads();

    const int tl = tid % TT;
    const int g  = tid / TT;              // k-group 0..9 (40 k each)

    float acc[8];
    #pragma unroll
    for (int b = 0; b < 8; b++) acc[b] = 0.f;

    const float* wp = fc1w + (size_t)(g * KG3) * HID + t0 + tl;

    #pragma unroll
    for (int kk = 0; kk < KG3 / 4; kk++) {       // 10 iterations of 4 k
        float w0 = wp[0];
        float w1 = wp[HID];
        float w2 = wp[2 * HID];
        float w3 = wp[3 * HID];
        wp += 4 * HID;
        #pragma unroll
        for (int b = 0; b < 8; b++) {
            float4 h = *(const float4*)(&H0s[b][g * KG3 + kk * 4]);
            acc[b] = fmaf(h.x, w0, acc[b]);
            acc[b] = fmaf(h.y, w1, acc[b]);
            acc[b] = fmaf(h.z, w2, acc[b]);
            acc[b] = fmaf(h.w, w3, acc[b]);
        }
    }
    #pragma unroll
    for (int b = 0; b < 8; b++) part[g][tl][b] = acc[b];
    __syncthreads();

    // combine k-groups, relu, * fc2w  (threads 0..TT-1)
    if (tid < TT) {
        int t = t0 + tid;
        float fb = fc1b[t], w2 = fc2w[t];
        #pragma unroll
        for (int b = 0; b < 8; b++) {
            float s = fb;
            #pragma unroll
            for (int gg = 0; gg < 10; gg++) s += part[gg][tid][b];
            part[0][tid][b] = fmaxf(s, 0.f) * w2;
        }
    }
    __syncthreads();

    // per-batch sum over the 80 t-lanes, atomic into global partials
    if (tid < 8) {
        float s = 0.f;
        #pragma unroll 8
        for (int t = 0; t < TT; t++) s += part[0][t][tid];
        atomicAdd(&g_Qs[b0 + tid], s);
    }
    __syncthreads();

    // last of the 5 t-tile blocks for this batch tile finalizes Q and G
    if (tid == 0) {
        __threadfence();
        unsigned int done = atomicAdd(&g_cnt[blockIdx.x], 1u);
        sflag = (done == 4u);
    }
    __syncthreads();
    if (sflag && tid < 8) {
        int b = b0 + tid;
        float q = g_Qs[b] + fc2b[0];
        Q_out[b] = q;
        G_out[b] = q + A_in[b];
    }
}

// ---------------- launch ------------------------------------------------------
extern "C" void kernel_launch(void* const* d_in, const int* in_sizes, int n_in,
                              void* d_out, int out_size) {
    const float* x     = (const float*)d_in[0];
    const float* a     = (const float*)d_in[1];
    const float* fp    = (const float*)d_in[2];
    const float* fc0w  = (const float*)d_in[4];
    const float* fc0b  = (const float*)d_in[5];
    const float* fc1w  = (const float*)d_in[6];
    const float* fc1b  = (const float*)d_in[7];
    const float* fc2w  = (const float*)d_in[8];
    const float* fc2b  = (const float*)d_in[9];
    const float* fc3w  = (const float*)d_in[10];
    const float* fc3b  = (const float*)d_in[11];
    const float* u1W   = (const float*)d_in[12];
    const float* u1a   = (const float*)d_in[13];
    const float* u2W   = (const float*)d_in[14];
    const float* d1W   = (const float*)d_in[16];
    const float* d1a   = (const float*)d_in[17];
    const float* d2W   = (const float*)d_in[18];

    float* out = (float*)d_out;
    float* Q   = out;            // [0,256)
    float* A   = out + 256;      // [256,512)
    float* G   = out + 512;      // [512,768)
    float* reg = out + 768;      // [768]

    k_prep<<<165, 256>>>(u1W, u1a, d1W, d1a, u2W, d2W, fc3w, reg,
                         x, a, fc0w, fc0b);
    k_attn<<<BQ, 256>>>(fp);
    k_gat2<<<BQ / 4, 512>>>(fp, u1W, d1W, fc3b, A);
    k_ego<<<dim3(BQ / 8, HID / TT), 800>>>(fc1w, fc1b, fc2w, fc2b, A, Q, G);
}

// round 11
// speedup vs baseline: 1.7494x; 1.7494x over previous
#include <cuda_runtime.h>
#include <cuda_bf16.h>
#include <cstdint>
#include <cstddef>

// Problem constants
#define BQ 256          // batch
#define NN 256          // nodes
#define FF 67           // fp feature stride
#define FEAT 64         // used features
#define HID 400
#define EGO 62          // STATE_DIM + 1
#define BFP (NN * FF)   // 17152 floats per batch in fp
#define CH 128          // nodes per smem chunk in k_attn

// fc1 GEMM tiling
#define TT 80           // t-outputs per block (5 tiles cover 400)
#define KG 100          // k per k-group (4 groups cover 400)

// ---------------- scratch (device globals; no allocs allowed) ----------------
__device__ float g_wl_u[FEAT], g_wr_u[FEAT], g_wl_d[FEAT], g_wr_d[FEAT];
__device__ float g_c2u[HID], g_c2d[HID];
__device__ float g_fbar_u[BQ * FEAT];
__device__ float g_fbar_d[BQ * FEAT];
__device__ float g_Qs[BQ];                       // fc2 partial sums (atomic)
__device__ unsigned int g_cnt[BQ / 8];           // finalize counters

__device__ __forceinline__ float eluf(float x) {
    return x > 0.f ? x : (expf(x) - 1.f);
}

// ---------------- K0: prep (warp-per-output) ---------------------------------
__global__ void __launch_bounds__(256) k_prep(
        const float* __restrict__ u1W, const float* __restrict__ u1a,
        const float* __restrict__ d1W, const float* __restrict__ d1a,
        const float* __restrict__ u2W, const float* __restrict__ d2W,
        const float* __restrict__ fc3w, float* __restrict__ reg_out) {
    const int warp = blockIdx.x * 8 + (threadIdx.x >> 5);
    const int lane = threadIdx.x & 31;

    if (warp < 1056) {
        const float* Wrow;
        const float* v;
        float* dst;
        if (warp < 256) {
            int which = warp >> 6, f = warp & 63;
            const float* W  = (which < 2) ? u1W : d1W;
            const float* av = (which < 2) ? u1a : d1a;
            Wrow = W + (size_t)f * HID;
            v    = av + ((which & 1) ? HID : 0);
            dst  = (which == 0) ? g_wl_u + f : (which == 1) ? g_wr_u + f
                 : (which == 2) ? g_wl_d + f : g_wr_d + f;
        } else {
            int k = warp - 256;
            const float* W = (k < HID) ? u2W : d2W;
            int kk = (k < HID) ? k : k - HID;
            Wrow = W + (size_t)kk * HID;
            v    = fc3w;
            dst  = (k < HID) ? g_c2u + kk : g_c2d + kk;
        }
        float s = 0.f;
        #pragma unroll
        for (int i = 0; i < 13; i++) {
            int idx = lane + 32 * i;
            if (idx < HID) s = fmaf(Wrow[idx], v[idx], s);
        }
        #pragma unroll
        for (int o = 16; o > 0; o >>= 1) s += __shfl_down_sync(0xffffffffu, s, o);
        if (lane == 0) *dst = s;
    } else if (warp == 1056) {
        for (int i = lane; i < BQ; i += 32) g_Qs[i] = 0.f;
        g_cnt[lane] = 0u;
        if (lane == 0) reg_out[0] = 0.f;
    }
}

// ---------------- K1: per-batch star attention -> featbar ---------------------
// smem-staged, coalesced loads; chunked to stay under 48KB static smem.
__global__ void __launch_bounds__(256) k_attn(const float* __restrict__ fp) {
    const int b = blockIdx.x, t = threadIdx.x;
    const int lane = t & 31, wid = t >> 5;

    __shared__ __align__(16) float buf[CH * FF];          // 34.3KB chunk
    __shared__ float wlu[FEAT], wru[FEAT], wld[FEAT], wrd[FEAT];
    __shared__ float au[NN], ad[NN];
    __shared__ float red[NN], red2[NN];
    __shared__ float sm8u[8], sm8d[8];
    __shared__ float scal[2];

    if (t < FEAT) { wlu[t] = g_wl_u[t]; wru[t] = g_wr_u[t];
                    wld[t] = g_wl_d[t]; wrd[t] = g_wr_d[t]; }

    // ---- pass 1: per-node e-scores (smem-staged) ----
    float su = 0.f, sd = 0.f, lu = 0.f, ld = 0.f;
    #pragma unroll
    for (int c = 0; c < 2; c++) {
        __syncthreads();
        const float4* src = (const float4*)(fp + (size_t)b * BFP + (size_t)c * CH * FF);
        float4* dbuf = (float4*)buf;
        #pragma unroll
        for (int i = 0; i < 9; i++) {
            int idx = t + 256 * i;
            if (idx < CH * FF / 4) dbuf[idx] = src[idx];
        }
        __syncthreads();
        if ((t >> 7) == c) {
            const int n = t & (CH - 1);
            const float* row = buf + n * FF;
            su = sd = lu = ld = 0.f;
            #pragma unroll 16
            for (int f = 0; f < FEAT; f++) {
                float v = row[f];
                su = fmaf(v, wru[f], su);
                sd = fmaf(v, wrd[f], sd);
                lu = fmaf(v, wlu[f], lu);
                ld = fmaf(v, wld[f], ld);
            }
            if (t == 0) { scal[0] = lu; scal[1] = ld; }
        }
    }
    __syncthreads();

    float eu = scal[0] + su;  eu = eu > 0.f ? eu : 0.2f * eu;
    float ed = scal[1] + sd;  ed = ed > 0.f ? ed : 0.2f * ed;
    if (t == 0) { eu = -1e30f; ed = -1e30f; }

    // ---- softmax via warp shuffles ----
    float mu = eu, md = ed;
    #pragma unroll
    for (int o = 16; o > 0; o >>= 1) {
        mu = fmaxf(mu, __shfl_xor_sync(0xffffffffu, mu, o));
        md = fmaxf(md, __shfl_xor_sync(0xffffffffu, md, o));
    }
    if (lane == 0) { sm8u[wid] = mu; sm8d[wid] = md; }
    __syncthreads();
    mu = sm8u[0]; md = sm8d[0];
    #pragma unroll
    for (int w = 1; w < 8; w++) { mu = fmaxf(mu, sm8u[w]); md = fmaxf(md, sm8d[w]); }

    float pu = expf(eu - mu), pd = expf(ed - md);
    float tu = pu, td = pd;
    #pragma unroll
    for (int o = 16; o > 0; o >>= 1) {
        tu += __shfl_xor_sync(0xffffffffu, tu, o);
        td += __shfl_xor_sync(0xffffffffu, td, o);
    }
    __syncthreads();
    if (lane == 0) { sm8u[wid] = tu; sm8d[wid] = td; }
    __syncthreads();
    tu = sm8u[0]; td = sm8d[0];
    #pragma unroll
    for (int w = 1; w < 8; w++) { tu += sm8u[w]; td += sm8d[w]; }

    au[t] = pu / tu;
    ad[t] = pd / td;

    // ---- pass 2: featbar = sum_j alpha_j * feat_j (re-stage chunks, L2-hit) --
    const int f = t & 63, g = t >> 6;    // 4 groups of 32 nodes per chunk
    float fu = 0.f, fd = 0.f;
    #pragma unroll
    for (int c = 0; c < 2; c++) {
        __syncthreads();
        const float4* src = (const float4*)(fp + (size_t)b * BFP + (size_t)c * CH * FF);
        float4* dbuf = (float4*)buf;
        #pragma unroll
        for (int i = 0; i < 9; i++) {
            int idx = t + 256 * i;
            if (idx < CH * FF / 4) dbuf[idx] = src[idx];
        }
        __syncthreads();
        const float* col = buf + (g * 32) * FF + f;
        const int jb = c * CH + g * 32;
        #pragma unroll 8
        for (int i = 0; i < 32; i++) {
            float v = col[i * FF];
            fu = fmaf(au[jb + i], v, fu);
            fd = fmaf(ad[jb + i], v, fd);
        }
    }
    red[t] = fu; red2[t] = fd; __syncthreads();
    if (t < 64) {
        g_fbar_u[b * FEAT + t] = red[t] + red[t + 64] + red[t + 128] + red[t + 192];
        g_fbar_d[b * FEAT + t] = red2[t] + red2[t + 64] + red2[t + 128] + red2[t + 192];
    }
}

// ---------------- K2: GAT layer1 matvecs + collapsed head -> A ----------------
__global__ void __launch_bounds__(512) k_gat2(const float* __restrict__ fp,
                                              const float* __restrict__ u1W,
                                              const float* __restrict__ d1W,
                                              const float* __restrict__ fc3b,
                                              float* __restrict__ A_out) {
    const int b0 = blockIdx.x * 4, t = threadIdx.x;
    __shared__ float x0[4][FEAT], xu[4][FEAT], xd[4][FEAT];
    __shared__ float c2u[HID], c2d[HID];
    __shared__ float sm_part[16][4];

    if (t < 256) {
        int r = t >> 6, f = t & 63;
        x0[r][f] = fp[(size_t)(b0 + r) * BFP + f];
        xu[r][f] = g_fbar_u[(b0 + r) * FEAT + f];
        xd[r][f] = g_fbar_d[(b0 + r) * FEAT + f];
    }
    if (t < HID) { c2u[t] = g_c2u[t]; c2d[t] = g_c2d[t]; }
    __syncthreads();

    float Av[4] = {0.f, 0.f, 0.f, 0.f};
    if (t < HID) {
        float a0[4] = {0.f, 0.f, 0.f, 0.f};
        float a1[4] = {0.f, 0.f, 0.f, 0.f};
        #pragma unroll 8
        for (int f = 0; f < FEAT; f++) {
            float w = u1W[f * HID + t];
            #pragma unroll
            for (int r = 0; r < 4; r++) {
                a0[r] = fmaf(x0[r][f], w, a0[r]);
                a1[r] = fmaf(xu[r][f], w, a1[r]);
            }
        }
        float cu = c2u[t];
        #pragma unroll
        for (int r = 0; r < 4; r++)
            Av[r] = (eluf(a0[r]) + 255.f * eluf(a1[r])) * cu;

        #pragma unroll
        for (int r = 0; r < 4; r++) { a0[r] = 0.f; a1[r] = 0.f; }
        #pragma unroll 8
        for (int f = 0; f < FEAT; f++) {
            float w = d1W[f * HID + t];
            #pragma unroll
            for (int r = 0; r < 4; r++) {
                a0[r] = fmaf(x0[r][f], w, a0[r]);
                a1[r] = fmaf(xd[r][f], w, a1[r]);
            }
        }
        float cd = c2d[t];
        #pragma unroll
        for (int r = 0; r < 4; r++)
            Av[r] += (eluf(a0[r]) + 255.f * eluf(a1[r])) * cd;
    }

    #pragma unroll
    for (int r = 0; r < 4; r++) {
        float s = Av[r];
        #pragma unroll
        for (int o = 16; o > 0; o >>= 1) s += __shfl_down_sync(0xffffffffu, s, o);
        if ((t & 31) == 0) sm_part[t >> 5][r] = s;
    }
    __syncthreads();
    if (t < 4) {
        float s = 0.f;
        #pragma unroll
        for (int wi = 0; wi < 16; wi++) s += sm_part[wi][t];
        A_out[b0 + t] = s + fc3b[0];
    }
}

// ---------------- K3: fused ego MLP (fc0+relu+fc1+relu+fc2) + finalize --------
// grid (32 batch-tiles, 5 t-tiles), 400 threads.
// Prologue (all 400 threads): H0s = relu(ego@fc0+b) in smem.
// Main (320 threads = 80 t-lanes x 4 k-groups): fc1 partial GEMM.
__global__ void __launch_bounds__(400) k_ego(const float* __restrict__ x,
                                             const float* __restrict__ a,
                                             const float* __restrict__ fc0w,
                                             const float* __restrict__ fc0b,
                                             const float* __restrict__ fc1w,
                                             const float* __restrict__ fc1b,
                                             const float* __restrict__ fc2w,
                                             const float* __restrict__ fc2b,
                                             const float* __restrict__ A_in,
                                             float* __restrict__ Q_out,
                                             float* __restrict__ G_out) {
    const int b0 = blockIdx.x * 8;
    const int t0 = blockIdx.y * TT;
    const int tid = threadIdx.x;

    __shared__ __align__(16) float egoT[EGO][8];     // [feat][batch]
    __shared__ __align__(16) float H0s[8][HID];      // relu(ego@fc0)
    __shared__ float part[4][TT][8];
    __shared__ int sflag;

    for (int i = tid; i < 8 * EGO; i += 400) {
        int b = i / EGO, f = i % EGO;
        egoT[f][b] = (f < 61) ? x[(size_t)(b0 + b) * 61 + f] : a[b0 + b];
    }
    __syncthreads();

    // ---- prologue: H0 (one k-column per thread, 8 batches) ----
    {
        float bias = fc0b[tid];
        float acc[8];
        #pragma unroll
        for (int b = 0; b < 8; b++) acc[b] = bias;
        #pragma unroll
        for (int f = 0; f < EGO; f++) {
            float w = fc0w[f * HID + tid];
            const float4* e4 = (const float4*)egoT[f];
            float4 e0 = e4[0], e1 = e4[1];
            acc[0] = fmaf(e0.x, w, acc[0]);
            acc[1] = fmaf(e0.y, w, acc[1]);
            acc[2] = fmaf(e0.z, w, acc[2]);
            acc[3] = fmaf(e0.w, w, acc[3]);
            acc[4] = fmaf(e1.x, w, acc[4]);
            acc[5] = fmaf(e1.y, w, acc[5]);
            acc[6] = fmaf(e1.z, w, acc[6]);
            acc[7] = fmaf(e1.w, w, acc[7]);
        }
        #pragma unroll
        for (int b = 0; b < 8; b++) H0s[b][tid] = fmaxf(acc[b], 0.f);
    }
    __syncthreads();

    // ---- fc1 partial GEMM ----
    if (tid < 320) {
        const int tl = tid % TT;
        const int g  = tid / TT;              // k-group 0..3

        float acc[8];
        #pragma unroll
        for (int b = 0; b < 8; b++) acc[b] = 0.f;

        const float* wp = fc1w + (size_t)(g * KG) * HID + t0 + tl;

        #pragma unroll 5
        for (int kk = 0; kk < KG / 4; kk++) {       // 25 iterations of 4 k
            float w0 = wp[0];
            float w1 = wp[HID];
            float w2 = wp[2 * HID];
            float w3 = wp[3 * HID];
            wp += 4 * HID;
            #pragma unroll
            for (int b = 0; b < 8; b++) {
                float4 h = *(const float4*)(&H0s[b][g * KG + kk * 4]);
                acc[b] = fmaf(h.x, w0, acc[b]);
                acc[b] = fmaf(h.y, w1, acc[b]);
                acc[b] = fmaf(h.z, w2, acc[b]);
                acc[b] = fmaf(h.w, w3, acc[b]);
            }
        }
        #pragma unroll
        for (int b = 0; b < 8; b++) part[g][tl][b] = acc[b];
    }
    __syncthreads();

    // combine k-groups, relu, * fc2w  (threads 0..TT-1)
    if (tid < TT) {
        int t = t0 + tid;
        float fb = fc1b[t], w2 = fc2w[t];
        #pragma unroll
        for (int b = 0; b < 8; b++) {
            float s = part[0][tid][b] + part[1][tid][b]
                    + part[2][tid][b] + part[3][tid][b] + fb;
            part[0][tid][b] = fmaxf(s, 0.f) * w2;
        }
    }
    __syncthreads();

    // per-batch sum over the 80 t-lanes, atomic into global partials
    if (tid < 8) {
        float s = 0.f;
        #pragma unroll 8
        for (int t = 0; t < TT; t++) s += part[0][t][tid];
        atomicAdd(&g_Qs[b0 + tid], s);
    }
    __syncthreads();

    // last of the 5 t-tile blocks for this batch tile finalizes Q and G
    if (tid == 0) {
        __threadfence();
        unsigned int done = atomicAdd(&g_cnt[blockIdx.x], 1u);
        sflag = (done == 4u);
    }
    __syncthreads();
    if (sflag && tid < 8) {
        int b = b0 + tid;
        float q = g_Qs[b] + fc2b[0];
        Q_out[b] = q;
        G_out[b] = q + A_in[b];
    }
}

// ---------------- launch ------------------------------------------------------
extern "C" void kernel_launch(void* const* d_in, const int* in_sizes, int n_in,
                              void* d_out, int out_size) {
    const float* x     = (const float*)d_in[0];
    const float* a     = (const float*)d_in[1];
    const float* fp    = (const float*)d_in[2];
    const float* fc0w  = (const float*)d_in[4];
    const float* fc0b  = (const float*)d_in[5];
    const float* fc1w  = (const float*)d_in[6];
    const float* fc1b  = (const float*)d_in[7];
    const float* fc2w  = (const float*)d_in[8];
    const float* fc2b  = (const float*)d_in[9];
    const float* fc3w  = (const float*)d_in[10];
    const float* fc3b  = (const float*)d_in[11];
    const float* u1W   = (const float*)d_in[12];
    const float* u1a   = (const float*)d_in[13];
    const float* u2W   = (const float*)d_in[14];
    const float* d1W   = (const float*)d_in[16];
    const float* d1a   = (const float*)d_in[17];
    const float* d2W   = (const float*)d_in[18];

    float* out = (float*)d_out;
    float* Q   = out;            // [0,256)
    float* A   = out + 256;      // [256,512)
    float* G   = out + 512;      // [512,768)
    float* reg = out + 768;      // [768]

    k_prep<<<133, 256>>>(u1W, u1a, d1W, d1a, u2W, d2W, fc3w, reg);
    k_attn<<<BQ, 256>>>(fp);
    k_gat2<<<BQ / 4, 512>>>(fp, u1W, d1W, fc3b, A);
    k_ego<<<dim3(BQ / 8, HID / TT), 400>>>(x, a, fc0w, fc0b, fc1w, fc1b,
                                           fc2w, fc2b, A, Q, G);
}

// round 13
// speedup vs baseline: 1.8429x; 1.0535x over previous
#include <cuda_runtime.h>
#include <cuda_bf16.h>
#include <cstdint>
#include <cstddef>

// Problem constants
#define BQ 256          // batch
#define NN 256          // nodes
#define FF 67           // fp feature stride
#define FEAT 64         // used features
#define HID 400
#define EGO 62          // STATE_DIM + 1
#define BFP (NN * FF)   // 17152 floats per batch in fp
#define CH 128          // nodes per smem chunk in k_attn

// fc1 GEMM tiling
#define TT 80           // t-outputs per block (5 tiles cover 400)
#define KG3 40          // k per k-group (10 groups cover 400)

// ---------------- scratch (device globals; no allocs allowed) ----------------
__device__ float g_wl_u[FEAT], g_wr_u[FEAT], g_wl_d[FEAT], g_wr_d[FEAT];
__device__ float g_c2u[HID], g_c2d[HID];
__device__ float g_fbar_u[BQ * FEAT];
__device__ float g_fbar_d[BQ * FEAT];
__device__ float g_Qs[BQ];                       // fc2 partial sums (atomic)
__device__ unsigned int g_cnt[BQ / 8];           // finalize counters

__device__ __forceinline__ float eluf(float x) {
    return x > 0.f ? x : (expf(x) - 1.f);
}

// ---------------- K0: prep (warp-per-output) ---------------------------------
__global__ void __launch_bounds__(256) k_prep(
        const float* __restrict__ u1W, const float* __restrict__ u1a,
        const float* __restrict__ d1W, const float* __restrict__ d1a,
        const float* __restrict__ u2W, const float* __restrict__ d2W,
        const float* __restrict__ fc3w, float* __restrict__ reg_out) {
    const int warp = blockIdx.x * 8 + (threadIdx.x >> 5);
    const int lane = threadIdx.x & 31;

    if (warp < 1056) {
        const float* Wrow;
        const float* v;
        float* dst;
        if (warp < 256) {
            int which = warp >> 6, f = warp & 63;
            const float* W  = (which < 2) ? u1W : d1W;
            const float* av = (which < 2) ? u1a : d1a;
            Wrow = W + (size_t)f * HID;
            v    = av + ((which & 1) ? HID : 0);
            dst  = (which == 0) ? g_wl_u + f : (which == 1) ? g_wr_u + f
                 : (which == 2) ? g_wl_d + f : g_wr_d + f;
        } else {
            int k = warp - 256;
            const float* W = (k < HID) ? u2W : d2W;
            int kk = (k < HID) ? k : k - HID;
            Wrow = W + (size_t)kk * HID;
            v    = fc3w;
            dst  = (k < HID) ? g_c2u + kk : g_c2d + kk;
        }
        float s = 0.f;
        #pragma unroll
        for (int i = 0; i < 13; i++) {
            int idx = lane + 32 * i;
            if (idx < HID) s = fmaf(Wrow[idx], v[idx], s);
        }
        #pragma unroll
        for (int o = 16; o > 0; o >>= 1) s += __shfl_down_sync(0xffffffffu, s, o);
        if (lane == 0) *dst = s;
    } else if (warp == 1056) {
        for (int i = lane; i < BQ; i += 32) g_Qs[i] = 0.f;
        g_cnt[lane] = 0u;
        if (lane == 0) reg_out[0] = 0.f;
    }
}

// ---------------- K1: per-batch star attention -> featbar ---------------------
// smem-staged, coalesced loads; chunked to stay under 48KB static smem.
__global__ void __launch_bounds__(256) k_attn(const float* __restrict__ fp) {
    const int b = blockIdx.x, t = threadIdx.x;
    const int lane = t & 31, wid = t >> 5;

    __shared__ __align__(16) float buf[CH * FF];          // 34.3KB chunk
    __shared__ float wlu[FEAT], wru[FEAT], wld[FEAT], wrd[FEAT];
    __shared__ float au[NN], ad[NN];
    __shared__ float red[NN], red2[NN];
    __shared__ float sm8u[8], sm8d[8];
    __shared__ float scal[2];

    if (t < FEAT) { wlu[t] = g_wl_u[t]; wru[t] = g_wr_u[t];
                    wld[t] = g_wl_d[t]; wrd[t] = g_wr_d[t]; }

    // ---- pass 1: per-node e-scores (smem-staged) ----
    float su = 0.f, sd = 0.f, lu = 0.f, ld = 0.f;
    #pragma unroll
    for (int c = 0; c < 2; c++) {
        __syncthreads();
        const float4* src = (const float4*)(fp + (size_t)b * BFP + (size_t)c * CH * FF);
        float4* dbuf = (float4*)buf;
        #pragma unroll
        for (int i = 0; i < 9; i++) {
            int idx = t + 256 * i;
            if (idx < CH * FF / 4) dbuf[idx] = src[idx];
        }
        __syncthreads();
        if ((t >> 7) == c) {
            const int n = t & (CH - 1);
            const float* row = buf + n * FF;
            su = sd = lu = ld = 0.f;
            #pragma unroll 16
            for (int f = 0; f < FEAT; f++) {
                float v = row[f];
                su = fmaf(v, wru[f], su);
                sd = fmaf(v, wrd[f], sd);
                lu = fmaf(v, wlu[f], lu);
                ld = fmaf(v, wld[f], ld);
            }
            if (t == 0) { scal[0] = lu; scal[1] = ld; }
        }
    }
    __syncthreads();

    float eu = scal[0] + su;  eu = eu > 0.f ? eu : 0.2f * eu;
    float ed = scal[1] + sd;  ed = ed > 0.f ? ed : 0.2f * ed;
    if (t == 0) { eu = -1e30f; ed = -1e30f; }

    // ---- softmax via warp shuffles ----
    float mu = eu, md = ed;
    #pragma unroll
    for (int o = 16; o > 0; o >>= 1) {
        mu = fmaxf(mu, __shfl_xor_sync(0xffffffffu, mu, o));
        md = fmaxf(md, __shfl_xor_sync(0xffffffffu, md, o));
    }
    if (lane == 0) { sm8u[wid] = mu; sm8d[wid] = md; }
    __syncthreads();
    mu = sm8u[0]; md = sm8d[0];
    #pragma unroll
    for (int w = 1; w < 8; w++) { mu = fmaxf(mu, sm8u[w]); md = fmaxf(md, sm8d[w]); }

    float pu = expf(eu - mu), pd = expf(ed - md);
    float tu = pu, td = pd;
    #pragma unroll
    for (int o = 16; o > 0; o >>= 1) {
        tu += __shfl_xor_sync(0xffffffffu, tu, o);
        td += __shfl_xor_sync(0xffffffffu, td, o);
    }
    __syncthreads();
    if (lane == 0) { sm8u[wid] = tu; sm8d[wid] = td; }
    __syncthreads();
    tu = sm8u[0]; td = sm8d[0];
    #pragma unroll
    for (int w = 1; w < 8; w++) { tu += sm8u[w]; td += sm8d[w]; }

    au[t] = pu / tu;
    ad[t] = pd / td;

    // ---- pass 2: featbar = sum_j alpha_j * feat_j (re-stage chunks, L2-hit) --
    const int f = t & 63, g = t >> 6;    // 4 groups of 32 nodes per chunk
    float fu = 0.f, fd = 0.f;
    #pragma unroll
    for (int c = 0; c < 2; c++) {
        __syncthreads();
        const float4* src = (const float4*)(fp + (size_t)b * BFP + (size_t)c * CH * FF);
        float4* dbuf = (float4*)buf;
        #pragma unroll
        for (int i = 0; i < 9; i++) {
            int idx = t + 256 * i;
            if (idx < CH * FF / 4) dbuf[idx] = src[idx];
        }
        __syncthreads();
        const float* col = buf + (g * 32) * FF + f;
        const int jb = c * CH + g * 32;
        #pragma unroll 8
        for (int i = 0; i < 32; i++) {
            float v = col[i * FF];
            fu = fmaf(au[jb + i], v, fu);
            fd = fmaf(ad[jb + i], v, fd);
        }
    }
    red[t] = fu; red2[t] = fd; __syncthreads();
    if (t < 64) {
        g_fbar_u[b * FEAT + t] = red[t] + red[t + 64] + red[t + 128] + red[t + 192];
        g_fbar_d[b * FEAT + t] = red2[t] + red2[t + 64] + red2[t + 128] + red2[t + 192];
    }
}

// ---------------- K2: GAT layer1 matvecs + collapsed head -> A ----------------
__global__ void __launch_bounds__(512) k_gat2(const float* __restrict__ fp,
                                              const float* __restrict__ u1W,
                                              const float* __restrict__ d1W,
                                              const float* __restrict__ fc3b,
                                              float* __restrict__ A_out) {
    const int b0 = blockIdx.x * 4, t = threadIdx.x;
    __shared__ float x0[4][FEAT], xu[4][FEAT], xd[4][FEAT];
    __shared__ float c2u[HID], c2d[HID];
    __shared__ float sm_part[16][4];

    if (t < 256) {
        int r = t >> 6, f = t & 63;
        x0[r][f] = fp[(size_t)(b0 + r) * BFP + f];
        xu[r][f] = g_fbar_u[(b0 + r) * FEAT + f];
        xd[r][f] = g_fbar_d[(b0 + r) * FEAT + f];
    }
    if (t < HID) { c2u[t] = g_c2u[t]; c2d[t] = g_c2d[t]; }
    __syncthreads();

    float Av[4] = {0.f, 0.f, 0.f, 0.f};
    if (t < HID) {
        float a0[4] = {0.f, 0.f, 0.f, 0.f};
        float a1[4] = {0.f, 0.f, 0.f, 0.f};
        #pragma unroll 8
        for (int f = 0; f < FEAT; f++) {
            float w = u1W[f * HID + t];
            #pragma unroll
            for (int r = 0; r < 4; r++) {
                a0[r] = fmaf(x0[r][f], w, a0[r]);
                a1[r] = fmaf(xu[r][f], w, a1[r]);
            }
        }
        float cu = c2u[t];
        #pragma unroll
        for (int r = 0; r < 4; r++)
            Av[r] = (eluf(a0[r]) + 255.f * eluf(a1[r])) * cu;

        #pragma unroll
        for (int r = 0; r < 4; r++) { a0[r] = 0.f; a1[r] = 0.f; }
        #pragma unroll 8
        for (int f = 0; f < FEAT; f++) {
            float w = d1W[f * HID + t];
            #pragma unroll
            for (int r = 0; r < 4; r++) {
                a0[r] = fmaf(x0[r][f], w, a0[r]);
                a1[r] = fmaf(xd[r][f], w, a1[r]);
            }
        }
        float cd = c2d[t];
        #pragma unroll
        for (int r = 0; r < 4; r++)
            Av[r] += (eluf(a0[r]) + 255.f * eluf(a1[r])) * cd;
    }

    #pragma unroll
    for (int r = 0; r < 4; r++) {
        float s = Av[r];
        #pragma unroll
        for (int o = 16; o > 0; o >>= 1) s += __shfl_down_sync(0xffffffffu, s, o);
        if ((t & 31) == 0) sm_part[t >> 5][r] = s;
    }
    __syncthreads();
    if (t < 4) {
        float s = 0.f;
        #pragma unroll
        for (int wi = 0; wi < 16; wi++) s += sm_part[wi][t];
        A_out[b0 + t] = s + fc3b[0];
    }
}

// ---------------- K3: fused ego MLP + finalize --------------------------------
// grid (32 batch-tiles, 5 t-tiles), 800 threads.
// Prologue (tid<400): H0s = relu(ego@fc0+b) in smem (as R4 baseline).
// Main (all 800 thr = 80 t-lanes x 10 k-groups of 40): fc1 partial GEMM,
// float4 smem loads (g*40 is 16B-aligned), fully unrolled inner loop.
__global__ void __launch_bounds__(800) k_ego(const float* __restrict__ x,
                                             const float* __restrict__ a,
                                             const float* __restrict__ fc0w,
                                             const float* __restrict__ fc0b,
                                             const float* __restrict__ fc1w,
                                             const float* __restrict__ fc1b,
                                             const float* __restrict__ fc2w,
                                             const float* __restrict__ fc2b,
                                             const float* __restrict__ A_in,
                                             float* __restrict__ Q_out,
                                             float* __restrict__ G_out) {
    const int b0 = blockIdx.x * 8;
    const int t0 = blockIdx.y * TT;
    const int tid = threadIdx.x;

    __shared__ __align__(16) float egoT[EGO][8];     // [feat][batch]  2KB
    __shared__ __align__(16) float H0s[8][HID];      // 12.8KB
    __shared__ float part[10][TT][8];                // 25.6KB
    __shared__ int sflag;

    for (int i = tid; i < 8 * EGO; i += 800) {
        int b = i / EGO, f = i % EGO;
        egoT[f][b] = (f < 61) ? x[(size_t)(b0 + b) * 61 + f] : a[b0 + b];
    }
    __syncthreads();

    // ---- prologue: H0 (one k-column per thread, 8 batches; tid<400) ----
    if (tid < HID) {
        float bias = fc0b[tid];
        float acc[8];
        #pragma unroll
        for (int b = 0; b < 8; b++) acc[b] = bias;
        #pragma unroll
        for (int f = 0; f < EGO; f++) {
            float w = fc0w[f * HID + tid];
            const float4* e4 = (const float4*)egoT[f];
            float4 e0 = e4[0], e1 = e4[1];
            acc[0] = fmaf(e0.x, w, acc[0]);
            acc[1] = fmaf(e0.y, w, acc[1]);
            acc[2] = fmaf(e0.z, w, acc[2]);
            acc[3] = fmaf(e0.w, w, acc[3]);
            acc[4] = fmaf(e1.x, w, acc[4]);
            acc[5] = fmaf(e1.y, w, acc[5]);
            acc[6] = fmaf(e1.z, w, acc[6]);
            acc[7] = fmaf(e1.w, w, acc[7]);
        }
        #pragma unroll
        for (int b = 0; b < 8; b++) H0s[b][tid] = fmaxf(acc[b], 0.f);
    }
    __syncthreads();

    // ---- fc1 partial GEMM: 80 t-lanes x 10 k-groups ----
    {
        const int tl = tid % TT;
        const int g  = tid / TT;              // k-group 0..9 (40 k each)

        float acc[8];
        #pragma unroll
        for (int b = 0; b < 8; b++) acc[b] = 0.f;

        const float* wp = fc1w + (size_t)(g * KG3) * HID + t0 + tl;

        #pragma unroll
        for (int kk = 0; kk < KG3 / 4; kk++) {       // 10 iterations of 4 k
            float w0 = wp[0];
            float w1 = wp[HID];
            float w2 = wp[2 * HID];
            float w3 = wp[3 * HID];
            wp += 4 * HID;
            #pragma unroll
            for (int b = 0; b < 8; b++) {
                float4 h = *(const float4*)(&H0s[b][g * KG3 + kk * 4]);
                acc[b] = fmaf(h.x, w0, acc[b]);
                acc[b] = fmaf(h.y, w1, acc[b]);
                acc[b] = fmaf(h.z, w2, acc[b]);
                acc[b] = fmaf(h.w, w3, acc[b]);
            }
        }
        #pragma unroll
        for (int b = 0; b < 8; b++) part[g][tl][b] = acc[b];
    }
    __syncthreads();

    // combine k-groups, relu, * fc2w  (threads 0..TT-1)
    if (tid < TT) {
        int t = t0 + tid;
        float fb = fc1b[t], w2 = fc2w[t];
        #pragma unroll
        for (int b = 0; b < 8; b++) {
            float s = fb;
            #pragma unroll
            for (int gg = 0; gg < 10; gg++) s += part[gg][tid][b];
            part[0][tid][b] = fmaxf(s, 0.f) * w2;
        }
    }
    __syncthreads();

    // per-batch sum over the 80 t-lanes, atomic into global partials
    if (tid < 8) {
        float s = 0.f;
        #pragma unroll 8
        for (int t = 0; t < TT; t++) s += part[0][t][tid];
        atomicAdd(&g_Qs[b0 + tid], s);
    }
    __syncthreads();

    // last of the 5 t-tile blocks for this batch tile finalizes Q and G
    if (tid == 0) {
        __threadfence();
        unsigned int done = atomicAdd(&g_cnt[blockIdx.x], 1u);
        sflag = (done == 4u);
    }
    __syncthreads();
    if (sflag && tid < 8) {
        int b = b0 + tid;
        float q = g_Qs[b] + fc2b[0];
        Q_out[b] = q;
        G_out[b] = q + A_in[b];
    }
}

// ---------------- launch ------------------------------------------------------
extern "C" void kernel_launch(void* const* d_in, const int* in_sizes, int n_in,
                              void* d_out, int out_size) {
    const float* x     = (const float*)d_in[0];
    const float* a     = (const float*)d_in[1];
    const float* fp    = (const float*)d_in[2];
    const float* fc0w  = (const float*)d_in[4];
    const float* fc0b  = (const float*)d_in[5];
    const float* fc1w  = (const float*)d_in[6];
    const float* fc1b  = (const float*)d_in[7];
    const float* fc2w  = (const float*)d_in[8];
    const float* fc2b  = (const float*)d_in[9];
    const float* fc3w  = (const float*)d_in[10];
    const float* fc3b  = (const float*)d_in[11];
    const float* u1W   = (const float*)d_in[12];
    const float* u1a   = (const float*)d_in[13];
    const float* u2W   = (const float*)d_in[14];
    const float* d1W   = (const float*)d_in[16];
    const float* d1a   = (const float*)d_in[17];
    const float* d2W   = (const float*)d_in[18];

    float* out = (float*)d_out;
    float* Q   = out;            // [0,256)
    float* A   = out + 256;      // [256,512)
    float* G   = out + 512;      // [512,768)
    float* reg = out + 768;      // [768]

    k_prep<<<133, 256>>>(u1W, u1a, d1W, d1a, u2W, d2W, fc3w, reg);
    k_attn<<<BQ, 256>>>(fp);
    k_gat2<<<BQ / 4, 512>>>(fp, u1W, d1W, fc3b, A);
    k_ego<<<dim3(BQ / 8, HID / TT), 800>>>(x, a, fc0w, fc0b, fc1w, fc1b,
                                           fc2w, fc2b, A, Q, G);
}